// round 7
// baseline (speedup 1.0000x reference)
#include <cuda_runtime.h>
#include <cuda_fp16.h>

#define BB 128
#define TT 512
#define CC 128

#define EBIAS 1.25f   // E' = exp(trans - EBIAS)
#define GROW  4.6f    // expected per-step log growth
#define BETA  0.75f   // renorm damping (poles |z|=0.866)
#define GAMMA 0.01f   // startup normalizer state

__device__ float g_partial[BB];

__device__ __forceinline__ float block_reduce_sum_256(float v, float* sh8) {
    #pragma unroll
    for (int o = 16; o > 0; o >>= 1)
        v += __shfl_xor_sync(0xffffffffu, v, o);
    int w = threadIdx.x >> 5;
    if ((threadIdx.x & 31) == 0) sh8[w] = v;
    __syncthreads();
    float r = ((sh8[0] + sh8[1]) + (sh8[2] + sh8[3]))
            + ((sh8[4] + sh8[5]) + (sh8[6] + sh8[7]));
    __syncthreads();
    return r;
}

__global__ __launch_bounds__(256, 1)
void crf_forward_kernel(const float* __restrict__ feats,
                        const int*   __restrict__ mask,
                        const int*   __restrict__ tags,
                        const float* __restrict__ trans)
{
    const int b   = blockIdx.x;
    const int tid = threadIdx.x;
    const int j   = tid & 127;     // class column
    const int h   = tid >> 7;      // i-half (0 or 1)

    __shared__ __align__(16) __half p_s[2][CC];
    __shared__ float red_s[256];
    __shared__ __align__(16) float shmax[2][4];
    __shared__ float sh8[8];

    // ---- sequence length ----
    const int* mrow = mask + b * TT;
    int cnt = mrow[tid] + mrow[tid + 256];
    const int L = (int)block_reduce_sum_256((float)cnt, sh8);

    // ---- E half-column, two complementarily-rounded fp16 copies ----
    // thread (j,h) owns i in [h*64, h*64+64)
    __half2 E2a[32], E2b[32];
    #pragma unroll
    for (int ii = 0; ii < 32; ii++) {
        int i0 = h * 64 + 2 * ii;
        float lo = __expf(trans[(i0 + 0) * CC + j] - EBIAS);  // exp(-1e5)->0
        float hi = __expf(trans[(i0 + 1) * CC + j] - EBIAS);
        __half hlo = __float2half_rn(lo), hhi = __float2half_rn(hi);
        E2a[ii] = __halves2half2(hlo, hhi);
        __half blo = __float2half_rn(2.0f * lo - __half2float(hlo));
        __half bhi = __float2half_rn(2.0f * hi - __half2float(hhi));
        E2b[ii] = __halves2half2(blo, bhi);
    }

    // ---- init ----
    if (h == 0) p_s[0][j] = __float2half_rn((j == CC - 2) ? 1.0f : 0.0f);
    if (tid < 4) { shmax[0][tid] = GAMMA; shmax[1][tid] = GAMMA; }
    __syncthreads();

    const float* fb = feats + (size_t)b * TT * CC + j;
    float m   = 0.0f;
    float ef0 = __expf(fb[0]);
    float ef1 = (L > 1) ? __expf(fb[CC]) : 1.0f;
    float vprev = GAMMA;
    int cur = 0;

    auto step = [&](const __half2 (&Ecol)[32], int t) {
        // lag-2 block max -> damped normalizer (off critical path)
        float4 mq = *(const float4*)shmax[(t ^ 1) & 1];
        float M2 = fmaxf(fmaxf(mq.x, mq.y), fmaxf(mq.z, mq.w));
        float lm    = __logf(M2);
        float inv_c = __expf(-GROW - BETA * lm);

        float ef2 = (t + 2 < L) ? __expf(fb[(size_t)(t + 2) * CC]) : 1.0f;

        // half-matvec: 32 HFMA2, 8 chains depth 4
        const uint4* pv = (const uint4*)(p_s[cur] + h * 64);
        __half2 acc[8];
        #pragma unroll
        for (int k = 0; k < 8; k++) acc[k] = __floats2half2_rn(0.f, 0.f);
        #pragma unroll
        for (int ii = 0; ii < 8; ii++) {
            uint4 q = pv[ii];
            __half2 p0 = *reinterpret_cast<__half2*>(&q.x);
            __half2 p1 = *reinterpret_cast<__half2*>(&q.y);
            __half2 p2 = *reinterpret_cast<__half2*>(&q.z);
            __half2 p3 = *reinterpret_cast<__half2*>(&q.w);
            acc[(4 * ii + 0) & 7] = __hfma2(p0, Ecol[4 * ii + 0], acc[(4 * ii + 0) & 7]);
            acc[(4 * ii + 1) & 7] = __hfma2(p1, Ecol[4 * ii + 1], acc[(4 * ii + 1) & 7]);
            acc[(4 * ii + 2) & 7] = __hfma2(p2, Ecol[4 * ii + 2], acc[(4 * ii + 2) & 7]);
            acc[(4 * ii + 3) & 7] = __hfma2(p3, Ecol[4 * ii + 3], acc[(4 * ii + 3) & 7]);
        }

        // warp-max of prev stored p (warps 0-3 only; hidden under other warps' issue)
        if (h == 0) {
            float wm = vprev;
            #pragma unroll
            for (int o = 16; o > 0; o >>= 1)
                wm = fmaxf(wm, __shfl_xor_sync(0xffffffffu, wm, o));
            if ((j & 31) == 0) shmax[t & 1][j >> 5] = wm;
        }

        // fp16 tree (7 HADD2) -> one H2F
        __half2 t4a = __hadd2(acc[0], acc[1]);
        __half2 t4b = __hadd2(acc[2], acc[3]);
        __half2 t4c = __hadd2(acc[4], acc[5]);
        __half2 t4d = __hadd2(acc[6], acc[7]);
        __half2 t2a = __hadd2(t4a, t4b);
        __half2 t2b = __hadd2(t4c, t4d);
        float2 ff = __half22float2(__hadd2(t2a, t2b));
        red_s[tid] = ff.x + ff.y;
        __syncthreads();

        // combine halves, scale, store
        float sfull = red_s[j] + red_s[j + 128];
        float pj = (sfull * ef0) * inv_c;
        if (h == 0) { p_s[cur ^ 1][j] = __float2half_rn(pj); vprev = pj; }
        m += (EBIAS + GROW) + BETA * lm;

        ef0 = ef1; ef1 = ef2;
        cur ^= 1;
        __syncthreads();
    };

    // ---- forward scan, alternating E copies (cancels fp16 rounding bias) ----
    int t = 0;
    while (t < L) {
        step(E2a, t); t++;
        if (t < L) { step(E2b, t); t++; }
    }

    // ---- logZ ----
    float contrib = (h == 0)
        ? __half2float(p_s[cur][j]) * __expf(trans[j * CC + (CC - 1)]) : 0.0f;
    float tot = block_reduce_sum_256(contrib, sh8);
    float logZ = m + __logf(tot);

    // ---- gold path score (fp32 exact) ----
    const int* tg = tags + b * TT;
    const float* fbase = feats + (size_t)b * TT * CC;
    float sc = 0.0f;
    for (int tt = tid; tt < L; tt += 256)
        sc += fbase[(size_t)tt * CC + tg[tt]];
    for (int k = tid; k <= L; k += 256) {
        int prev = (k == 0) ? (CC - 2) : tg[k - 1];
        int curt = (k == L) ? (CC - 1) : tg[k];
        sc += trans[prev * CC + curt];
    }
    float tots = block_reduce_sum_256(sc, sh8);

    if (tid == 0) g_partial[b] = logZ - tots;
}

__global__ void crf_finalize_kernel(float* __restrict__ out)
{
    __shared__ float s[BB];
    int tid = threadIdx.x;
    s[tid] = g_partial[tid];
    __syncthreads();
    #pragma unroll
    for (int off = 64; off > 0; off >>= 1) {
        if (tid < off) s[tid] += s[tid + off];
        __syncthreads();
    }
    if (tid == 0) out[0] = s[0] / (float)BB;
}

extern "C" void kernel_launch(void* const* d_in, const int* in_sizes, int n_in,
                              void* d_out, int out_size)
{
    const float* feats = (const float*)d_in[0];
    const int*   mask  = (const int*)  d_in[1];
    const int*   tags  = (const int*)  d_in[2];
    const float* trans = (const float*)d_in[3];
    float* out = (float*)d_out;

    crf_forward_kernel<<<BB, 256>>>(feats, mask, tags, trans);
    crf_finalize_kernel<<<1, BB>>>(out);
}

// round 10
// speedup vs baseline: 1.2923x; 1.2923x over previous
#include <cuda_runtime.h>

#define BB 128
#define TT 512
#define CC 128

#define BARX(id) asm volatile("bar.sync %0, %1;" :: "r"(id), "r"(128) : "memory")

__device__ float g_partial[BB];

__device__ __forceinline__ float block_reduce_sum_256(float v, float* sh8) {
    #pragma unroll
    for (int o = 16; o > 0; o >>= 1)
        v += __shfl_xor_sync(0xffffffffu, v, o);
    int w = threadIdx.x >> 5;
    if ((threadIdx.x & 31) == 0) sh8[w] = v;
    __syncthreads();
    float r = ((sh8[0] + sh8[1]) + (sh8[2] + sh8[3]))
            + ((sh8[4] + sh8[5]) + (sh8[6] + sh8[7]));
    __syncthreads();
    return r;
}

__global__ __launch_bounds__(256, 1)
void crf_forward_kernel(const float* __restrict__ feats,
                        const int*   __restrict__ mask,
                        const int*   __restrict__ tags,
                        const float* __restrict__ trans)
{
    const int b   = blockIdx.x;
    const int tid = threadIdx.x;
    const int j   = tid & 127;     // class index owned
    const int h   = tid >> 7;      // 0 = forward chain, 1 = backward chain

    __shared__ __align__(16) float p_f[2][CC];   // scaled alpha
    __shared__ __align__(16) float p_b[2][CC];   // scaled beta
    __shared__ float sh8[8];
    __shared__ float sh_m[2];

    // ---- sequence length (contiguous prefix mask) ----
    const int* mrow = mask + b * TT;
    int cnt = mrow[tid] + mrow[tid + 256];
    const int L  = (int)block_reduce_sum_256((float)cnt, sh8);
    const int tm = L >> 1;                    // forward steps; backward = L-tm >= 1
    const int niter = (h == 0) ? tm : (L - tm);

    // ---- E in fp32 registers: forward thread = column j, backward thread = row j ----
    float Ereg[CC];
    #pragma unroll
    for (int i = 0; i < CC; i++) {
        int idx = (h == 0) ? (i * CC + j) : (j * CC + i);
        Ereg[i] = __expf(trans[idx]);         // exp(-1e5) -> 0 exactly
    }

    const float* fb = feats + (size_t)b * TT * CC + j;

    // ---- per-chain init ----
    // forward : alpha0 = onehot(START); iteration t multiplies by ef row t (t < tm)
    // backward: q0 = ef_{L-1} (.) exp(trans[.,STOP]); iteration t multiplies by
    //           ef row L-2-t for t <= niter-2; final iteration bare (gives beta_tm)
    float m = 0.0f, ef0, ef1;
    if (h == 0) {
        p_f[0][j] = (j == CC - 2) ? 1.0f : 0.0f;
        ef0 = (niter >= 1) ? __expf(fb[0])  : 1.0f;
        ef1 = (niter >= 2) ? __expf(fb[CC]) : 1.0f;
    } else {
        p_b[0][j] = __expf(fb[(size_t)(L - 1) * CC] + trans[j * CC + (CC - 1)]);
        ef0 = (niter >= 2) ? __expf(fb[(size_t)(L - 2) * CC]) : 1.0f;
        ef1 = (niter >= 3) ? __expf(fb[(size_t)(L - 3) * CC]) : 1.0f;
    }
    __syncthreads();

    // ---- hot loops: independent chains, one named barrier per step ----
    {
        float (*ps)[CC] = (h == 0) ? p_f : p_b;
        const int barid = 1 + h;
        int cur = 0;

        for (int t = 0; t < niter; t++) {
            // scale: previous stored p[0] (broadcast LDS; forward init has p[0]=0 -> use 1)
            float c  = (h == 0 && t == 0) ? 1.0f : ps[cur][0];
            float rc = __fdividef(1.0f, c);

            float ef2;
            if (h == 0)
                ef2 = (t + 2 < niter) ? __expf(fb[(size_t)(t + 2) * CC]) : 1.0f;
            else
                ef2 = (t + 2 <= niter - 2) ? __expf(fb[(size_t)(L - 4 - t) * CC]) : 1.0f;

            // matvec: s = sum_i ps[i] * Ereg[i]
            const float4* pv = (const float4*)ps[cur];
            float a0 = 0.f, a1 = 0.f, a2 = 0.f, a3 = 0.f;
            #pragma unroll
            for (int ii = 0; ii < 32; ii++) {
                float4 p4 = pv[ii];
                a0 = fmaf(p4.x, Ereg[4 * ii + 0], a0);
                a1 = fmaf(p4.y, Ereg[4 * ii + 1], a1);
                a2 = fmaf(p4.z, Ereg[4 * ii + 2], a2);
                a3 = fmaf(p4.w, Ereg[4 * ii + 3], a3);
            }
            float s = (a0 + a1) + (a2 + a3);

            ps[cur ^ 1][j] = (s * ef0) * rc;
            m += __logf(c);

            ef0 = ef1; ef1 = ef2;
            cur ^= 1;
            BARX(barid);
        }

        if (j == 0) sh_m[h] = m;
    }
    __syncthreads();

    // ---- meet in the middle: logZ = m_f + m_b + log( alpha~_tm . beta~_tm ) ----
    float contrib = (h == 0)
        ? p_f[tm & 1][j] * p_b[(L - tm) & 1][j] : 0.0f;
    float dot = block_reduce_sum_256(contrib, sh8);
    float logZ = sh_m[0] + sh_m[1] + __logf(dot);

    // ---- gold path score (fp32 exact) ----
    const int* tg = tags + b * TT;
    const float* fbase = feats + (size_t)b * TT * CC;
    float sc = 0.0f;
    for (int tt = tid; tt < L; tt += 256)
        sc += fbase[(size_t)tt * CC + tg[tt]];
    for (int k = tid; k <= L; k += 256) {
        int prev = (k == 0) ? (CC - 2) : tg[k - 1];
        int curt = (k == L) ? (CC - 1) : tg[k];
        sc += trans[prev * CC + curt];
    }
    float tots = block_reduce_sum_256(sc, sh8);

    if (tid == 0) g_partial[b] = logZ - tots;
}

__global__ void crf_finalize_kernel(float* __restrict__ out)
{
    __shared__ float s[BB];
    int tid = threadIdx.x;
    s[tid] = g_partial[tid];
    __syncthreads();
    #pragma unroll
    for (int off = 64; off > 0; off >>= 1) {
        if (tid < off) s[tid] += s[tid + off];
        __syncthreads();
    }
    if (tid == 0) out[0] = s[0] / (float)BB;
}

extern "C" void kernel_launch(void* const* d_in, const int* in_sizes, int n_in,
                              void* d_out, int out_size)
{
    const float* feats = (const float*)d_in[0];
    const int*   mask  = (const int*)  d_in[1];
    const int*   tags  = (const int*)  d_in[2];
    const float* trans = (const float*)d_in[3];
    float* out = (float*)d_out;

    crf_forward_kernel<<<BB, 256>>>(feats, mask, tags, trans);
    crf_finalize_kernel<<<1, BB>>>(out);
}